// round 15
// baseline (speedup 1.0000x reference)
#include <cuda_runtime.h>
#include <stdint.h>

#define Bb   64
#define Tt   128
#define Ee   256
#define Hh   512
#define G4H  2048
#define GSZ  (Tt*Bb*G4H)   /* 16,777,216 floats per gate buffer */

typedef unsigned long long u64;

// ---------------- scratch (__device__ globals: allocation-free) ----------------
__device__ float  g_x0[Tt*Bb*Ee];                // embedded inputs  [T*B, E]
__device__ float  g_x1[Tt*Bb*2*Hh];              // layer-0 outputs  [T*B, 2H]
__device__ float  g_G[(size_t)4*GSZ];            // gate pre-acts: G0f,G0b,G1f,G1b
__device__ float2 g_WB[4][64*4*64*32];           // Whh tf32 frag pack [sub][g][kb][lane]
__device__ float4 g_hQh[4][2][8192];             // h hi (tf32) frag quads, ping-pong
__device__ uint2  g_hQl2[4][2][8192];            // h lo residual, bf16x2-packed quads
__device__ float  g_hT[4][Hh*Bb];                // final h [k][b] (logits only)
__device__ float  g_c[4][Bb*Hh];                 // c state per sequence
__device__ unsigned g_bar[2][2];                 // [layer][dir] barrier counters

// ---------------- helpers ----------------
__device__ __forceinline__ float sigm(float x) { return 1.f / (1.f + __expf(-x)); }
__device__ __forceinline__ float tanh_fast(float x) {
    float xc = fminf(fmaxf(x, -15.f), 15.f);
    float e = __expf(-2.f * xc);
    return __fdividef(1.f - e, 1.f + e);
}
__device__ __forceinline__ uint32_t f2tf32(float x) {
    uint32_t r; asm("cvt.rna.tf32.f32 %0, %1;" : "=r"(r) : "f"(x)); return r;
}
__device__ __forceinline__ uint32_t fu(float x) { return __float_as_uint(x); }
__device__ __forceinline__ uint32_t pack_bf2(float c0, float c1) {
    uint32_t w;  // high half = c1, low half = c0
    asm("cvt.rn.bf16x2.f32 %0, %1, %2;" : "=r"(w) : "f"(c1), "f"(c0));
    return w;
}
__device__ __forceinline__ float bf_lo(uint32_t w) { return __uint_as_float(w << 16); }
__device__ __forceinline__ float bf_hi(uint32_t w) { return __uint_as_float(w & 0xffff0000u); }
__device__ __forceinline__ void mma_tf32(float* c,
        uint32_t a0, uint32_t a1, uint32_t a2, uint32_t a3,
        uint32_t b0, uint32_t b1) {
    asm volatile("mma.sync.aligned.m16n8k8.row.col.f32.tf32.tf32.f32 "
        "{%0,%1,%2,%3}, {%4,%5,%6,%7}, {%8,%9}, {%0,%1,%2,%3};"
        : "+f"(c[0]), "+f"(c[1]), "+f"(c[2]), "+f"(c[3])
        : "r"(a0), "r"(a1), "r"(a2), "r"(a3), "r"(b0), "r"(b1));
}

// ---------------- init: zero hQ (both parities, hi+lo), c, barriers ----------------
__global__ void init_states() {
    int i = blockIdx.x * blockDim.x + threadIdx.x;
    if (i < 4*2*8192*4) ((float*)g_hQh)[i] = 0.f;
    if (i < 4*2*8192)   ((uint2*)g_hQl2)[i] = make_uint2(0u, 0u);
    if (i < 4*Bb*Hh)    ((float*)g_c)[i] = 0.f;
    if (i < 4)          ((unsigned*)g_bar)[i] = 0u;
}

// ---------------- Whh -> per-(block,gate,k8) tf32 fragment pack ----------------
__global__ void pack_WB(const float* __restrict__ W0, const float* __restrict__ W1,
                        const float* __restrict__ W2, const float* __restrict__ W3) {
    int idx = blockIdx.x * blockDim.x + threadIdx.x;   // 2,097,152
    int lane = idx & 31;
    int kb   = (idx >> 5) & 63;
    int g    = (idx >> 11) & 3;
    int sub  = (idx >> 13) & 63;
    int seq  = idx >> 19;
    const float* W = (seq == 0) ? W0 : (seq == 1) ? W1 : (seq == 2) ? W2 : W3;
    int gid = lane >> 2, tig = lane & 3;
    int j = g * Hh + sub * 8 + gid;
    int k = kb * 8 + tig;
    float v0 = W[(size_t)j * Hh + k];
    float v1 = W[(size_t)j * Hh + k + 4];
    g_WB[seq][(((sub * 4 + g) * 64 + kb) * 32) + lane] =
        make_float2(__uint_as_float(f2tf32(v0)), __uint_as_float(f2tf32(v1)));
}

// ---------------- embedding gather ----------------
__global__ void gather_embed(const int* __restrict__ q, const float* __restrict__ emb) {
    int r = blockIdx.x;              // r = t*B + b
    int b = r & (Bb - 1);
    int t = r >> 6;
    int qi = q[b * Tt + t];
    const float4* src = (const float4*)(emb + (size_t)qi * Ee);
    float4* dst = (float4*)(g_x0 + (size_t)r * Ee);
    dst[threadIdx.x] = src[threadIdx.x];
}

// ---------------- feedforward GEMM: wide warp tile 64x64, BK=8 ----------------
// Block 128m x 256n, 8 warps (2m x 4n). Per k8 per warp: 16 A-LDS + 16 B-LDS for
// 32 mma (ratio 1.0 vs 1.5 before). A panels read by 8 n-blocks (was 16).
__global__ __launch_bounds__(256, 1) void sgemm_tf32w(int asel, int gsel, int K,
        const float* __restrict__ W,
        const float* __restrict__ b1, const float* __restrict__ b2)
{
    const float* __restrict__ A = asel ? g_x1 : g_x0;
    float* __restrict__ C = g_G + (size_t)gsel * GSZ;

    __shared__ uint32_t As[2][8*132];    //  8,448 B
    __shared__ uint32_t Bs[2][8*260];    // 16,640 B

    const int tid = threadIdx.x;
    const int m0 = blockIdx.y * 128, n0 = blockIdx.x * 256;
    const int w = tid >> 5, lane = tid & 31;
    const int gid = lane >> 2, tig = lane & 3;
    const int wm = (w & 1) * 64;
    const int wn = (w >> 1) * 64;

    float acc[4][8][4];
#pragma unroll
    for (int mt = 0; mt < 4; mt++)
#pragma unroll
        for (int nt = 0; nt < 8; nt++)
#pragma unroll
            for (int i = 0; i < 4; i++) acc[mt][nt][i] = 0.f;

    const int sr = tid >> 1;             // 0..127
    const int sc = (tid & 1) * 4;        // 0 or 4
    const float* Ar  = A + (size_t)(m0 + sr) * K + sc;
    const float* Wr0 = W + (size_t)(n0 + sr) * K + sc;
    const float* Wr1 = W + (size_t)(n0 + sr + 128) * K + sc;

#define STAGEW(bsel, va, vb0, vb1) { \
    As[bsel][(sc+0)*132 + sr] = f2tf32(va.x); \
    As[bsel][(sc+1)*132 + sr] = f2tf32(va.y); \
    As[bsel][(sc+2)*132 + sr] = f2tf32(va.z); \
    As[bsel][(sc+3)*132 + sr] = f2tf32(va.w); \
    Bs[bsel][(sc+0)*260 + sr]       = f2tf32(vb0.x); \
    Bs[bsel][(sc+1)*260 + sr]       = f2tf32(vb0.y); \
    Bs[bsel][(sc+2)*260 + sr]       = f2tf32(vb0.z); \
    Bs[bsel][(sc+3)*260 + sr]       = f2tf32(vb0.w); \
    Bs[bsel][(sc+0)*260 + sr + 128] = f2tf32(vb1.x); \
    Bs[bsel][(sc+1)*260 + sr + 128] = f2tf32(vb1.y); \
    Bs[bsel][(sc+2)*260 + sr + 128] = f2tf32(vb1.z); \
    Bs[bsel][(sc+3)*260 + sr + 128] = f2tf32(vb1.w); }

    {
        float4 va  = *(const float4*)Ar;
        float4 vb0 = *(const float4*)Wr0;
        float4 vb1 = *(const float4*)Wr1;
        STAGEW(0, va, vb0, vb1);
    }
    __syncthreads();

    int buf = 0;
    for (int kt = 0; kt < K; kt += 8) {
        float4 va, vb0, vb1;
        bool more = (kt + 8 < K);
        if (more) {
            va  = *(const float4*)(Ar + kt + 8);
            vb0 = *(const float4*)(Wr0 + kt + 8);
            vb1 = *(const float4*)(Wr1 + kt + 8);
        }
        // fragment loads
        uint32_t af[4][4], bf[8][2];
        const uint32_t* a_lo = &As[buf][tig * 132 + wm + gid];
        const uint32_t* a_hi = &As[buf][(tig + 4) * 132 + wm + gid];
        const uint32_t* b_lo = &Bs[buf][tig * 260 + wn + gid];
        const uint32_t* b_hi = &Bs[buf][(tig + 4) * 260 + wn + gid];
#pragma unroll
        for (int mt = 0; mt < 4; mt++) {
            af[mt][0] = a_lo[mt*16];
            af[mt][1] = a_lo[mt*16 + 8];
            af[mt][2] = a_hi[mt*16];
            af[mt][3] = a_hi[mt*16 + 8];
        }
#pragma unroll
        for (int nt = 0; nt < 8; nt++) {
            bf[nt][0] = b_lo[nt*8];
            bf[nt][1] = b_hi[nt*8];
        }
#pragma unroll
        for (int mt = 0; mt < 4; mt++)
#pragma unroll
            for (int nt = 0; nt < 8; nt++)
                mma_tf32(acc[mt][nt], af[mt][0], af[mt][1], af[mt][2], af[mt][3],
                         bf[nt][0], bf[nt][1]);
        if (more) {
            STAGEW(buf ^ 1, va, vb0, vb1);
            __syncthreads();
            buf ^= 1;
        }
    }
#undef STAGEW

#pragma unroll
    for (int nt = 0; nt < 8; nt++) {
        int gn = n0 + wn + nt * 8 + 2 * tig;
        float bs0 = b1[gn]   + b2[gn];
        float bs1 = b1[gn+1] + b2[gn+1];
#pragma unroll
        for (int mt = 0; mt < 4; mt++) {
            int gm = m0 + wm + mt * 16 + gid;
            float* c0 = C + (size_t)gm * G4H + gn;
            float* c1 = C + (size_t)(gm + 8) * G4H + gn;
            c0[0] = acc[mt][nt][0] + bs0;
            c0[1] = acc[mt][nt][1] + bs1;
            c1[0] = acc[mt][nt][2] + bs0;
            c1[1] = acc[mt][nt][3] + bs1;
        }
    }
}

// ---------------- per-direction software barrier (release/acquire) ----------------
__device__ __forceinline__ void dirbar(unsigned* ctr, unsigned target) {
    __syncthreads();
    if (threadIdx.x == 0) {
        asm volatile("red.release.gpu.global.add.u32 [%0], %1;"
                     :: "l"(ctr), "r"(1u) : "memory");
        unsigned v;
        do {
            asm volatile("ld.acquire.gpu.global.u32 %0, [%1];"
                         : "=r"(v) : "l"(ctr) : "memory");
            if (v >= target) break;
            __nanosleep(32);
        } while (true);
    }
    __syncthreads();
}

// ---------------- persistent recurrence (R14: split-h tf32, bf16 lo, staged WB) -------
__global__ __launch_bounds__(256, 1) void lstm_persist(int layer)
{
    __shared__ float gs[2][64 * 34];             // 17,408 B
    __shared__ float sh_hi[512];                 // h hi staging (frag order)
    __shared__ float sh_lo[512];                 // h lo staging (frag order)

    const int tid = threadIdx.x;
    const int dir = blockIdx.x >> 6;
    const int sub = blockIdx.x & 63;
    const int seq = layer * 2 + dir;
    const int w = tid >> 5, lane = tid & 31;
    const int kh = w & 1, mt = w >> 1;           // k-half, m16 tile
    const int gid = lane >> 2, tig = lane & 3;
    const int n0 = sub * 8;

    const float2* __restrict__ WB = g_WB[seq];
    float* __restrict__ cs = g_c[seq];
    const float* __restrict__ Gseq = g_G + (size_t)seq * GSZ;
    unsigned* bar = &g_bar[layer][dir];

    const int ew_m = tid >> 2;                   // 0..63
    const int u2 = (tid & 3) * 2;                // 0,2,4,6

    const float2* Bp0 = WB + (size_t)(((sub * 4 + 0) * 64) * 32) + lane;
    const float2* Bp1 = WB + (size_t)(((sub * 4 + 1) * 64) * 32) + lane;
    const float2* Bp2 = WB + (size_t)(((sub * 4 + 2) * 64) * 32) + lane;
    const float2* Bp3 = WB + (size_t)(((sub * 4 + 3) * 64) * 32) + lane;

#define IDXA(kb) ((((kb) * 4 + tig) * 4 + mt) * 8 + gid)

    for (int s = 0; s < Tt; s++) {
        const int t = dir ? (Tt - 1 - s) : s;
        const int p = s & 1;
        const float4* __restrict__ Hhi = g_hQh[seq][p];
        const uint2*  __restrict__ Hlo = g_hQl2[seq][p];
        float4* __restrict__ WHq = g_hQh[seq][p ^ 1];
        uint2*  __restrict__ WLq = g_hQl2[seq][p ^ 1];

        // ---------- prefetch gate pre-acts (DRAM) ----------
        const float* Gt = Gseq + (size_t)t * Bb * G4H;
        float2 gpre[4];
#pragma unroll
        for (int g = 0; g < 4; g++)
            gpre[g] = __ldcg((const float2*)&Gt[(size_t)ew_m * G4H + g * Hh + n0 + u2]);

        // ---------- tensor-core GEMM over this k-half ----------
        float acc[4][4];
#pragma unroll
        for (int g = 0; g < 4; g++)
#pragma unroll
            for (int i = 0; i < 4; i++) acc[g][i] = 0.f;

        const int kb0 = kh * 32;
        float4 ah = __ldcg(Hhi + IDXA(kb0));
        uint2  alw = __ldcg(Hlo + IDXA(kb0));
#pragma unroll 4
        for (int i = 0; i < 32; i++) {
            const int kb = kb0 + i;
            float4 ah2; uint2 alw2;
            if (i + 1 < 32) {
                ah2  = __ldcg(Hhi + IDXA(kb + 1));
                alw2 = __ldcg(Hlo + IDXA(kb + 1));
            }
            float2 b0 = Bp0[kb * 32];
            float2 b1 = Bp1[kb * 32];
            float2 b2 = Bp2[kb * 32];
            float2 b3 = Bp3[kb * 32];
            float l0 = bf_lo(alw.x), l1 = bf_hi(alw.x);
            float l2 = bf_lo(alw.y), l3 = bf_hi(alw.y);
            mma_tf32(acc[0], fu(ah.x), fu(ah.y), fu(ah.z), fu(ah.w), fu(b0.x), fu(b0.y));
            mma_tf32(acc[1], fu(ah.x), fu(ah.y), fu(ah.z), fu(ah.w), fu(b1.x), fu(b1.y));
            mma_tf32(acc[2], fu(ah.x), fu(ah.y), fu(ah.z), fu(ah.w), fu(b2.x), fu(b2.y));
            mma_tf32(acc[3], fu(ah.x), fu(ah.y), fu(ah.z), fu(ah.w), fu(b3.x), fu(b3.y));
            mma_tf32(acc[0], fu(l0), fu(l1), fu(l2), fu(l3), fu(b0.x), fu(b0.y));
            mma_tf32(acc[1], fu(l0), fu(l1), fu(l2), fu(l3), fu(b1.x), fu(b1.y));
            mma_tf32(acc[2], fu(l0), fu(l1), fu(l2), fu(l3), fu(b2.x), fu(b2.y));
            mma_tf32(acc[3], fu(l0), fu(l1), fu(l2), fu(l3), fu(b3.x), fu(b3.y));
            ah = ah2; alw = alw2;
        }

        // ---------- epilogue: write k-half slab ----------
        {
            int mrow = mt * 16 + gid;
#pragma unroll
            for (int g = 0; g < 4; g++) {
                *(float2*)&gs[kh][mrow * 34 + g * 8 + 2 * tig] =
                    make_float2(acc[g][0], acc[g][1]);
                *(float2*)&gs[kh][(mrow + 8) * 34 + g * 8 + 2 * tig] =
                    make_float2(acc[g][2], acc[g][3]);
            }
        }
        __syncthreads();

        // ---------- k-reduce (2 slabs) + input proj + fused LSTM elementwise ----------
        {
            float2 pre[4];
#pragma unroll
            for (int g = 0; g < 4; g++) {
                float2 p0 = *(const float2*)&gs[0][ew_m * 34 + g * 8 + u2];
                float2 p1 = *(const float2*)&gs[1][ew_m * 34 + g * 8 + u2];
                pre[g] = make_float2(gpre[g].x + p0.x + p1.x, gpre[g].y + p0.y + p1.y);
            }
            int ci = ew_m * Hh + n0 + u2;
            float2 c2 = *(float2*)&cs[ci];
            float hn[2], cn[2];
#pragma unroll
            for (int e = 0; e < 2; e++) {
                float pi = e ? pre[0].y : pre[0].x;
                float pf = e ? pre[1].y : pre[1].x;
                float pg = e ? pre[2].y : pre[2].x;
                float po = e ? pre[3].y : pre[3].x;
                float cp = e ? c2.y : c2.x;
                float i_s = sigm(pi), f_s = sigm(pf);
                float g_t = tanh_fast(pg), o_s = sigm(po);
                cn[e] = f_s * cp + i_s * g_t;
                hn[e] = o_s * tanh_fast(cn[e]);
            }
            *(float2*)&cs[ci] = make_float2(cn[0], cn[1]);
            if (layer == 0)
                *(float2*)&g_x1[((size_t)t * Bb + ew_m) * (2*Hh) + dir * Hh + n0 + u2] =
                    make_float2(hn[0], hn[1]);
            // stage hi/lo into smem in fragment order
#pragma unroll
            for (int e = 0; e < 2; e++) {
                int u = u2 + e;
                int tg = u & 3, zs = u >> 2;
                int comp = zs * 2 + ((ew_m >> 3) & 1);
                int idx = ((tg * 4 + (ew_m >> 4)) * 8 + (ew_m & 7)) * 4 + comp;
                float hv = __uint_as_float(f2tf32(hn[e]));
                sh_hi[idx] = hv;
                sh_lo[idx] = hn[e] - hv;
            }
            if (s == Tt - 1) {
                g_hT[seq][(n0 + u2) * Bb + ew_m]     = hn[0];
                g_hT[seq][(n0 + u2 + 1) * Bb + ew_m] = hn[1];
            }
        }
        __syncthreads();

        // ---------- vectorized fragment writeback (coalesced) ----------
        if (tid < 128) {
            WHq[sub * 128 + tid] = *(const float4*)&sh_hi[tid * 4];
        } else {
            int qi = tid - 128;
            const float* lp = &sh_lo[qi * 4];
            uint2 ov;
            ov.x = pack_bf2(lp[0], lp[1]);
            ov.y = pack_bf2(lp[2], lp[3]);
            WLq[sub * 128 + qi] = ov;
        }

        dirbar(bar, 64u * (s + 1));   // h_{s+1} (opposite parity) complete before s+1
    }
#undef IDXA
}

// ---------------- output head: logits + log_softmax ----------------
__global__ void logits_kernel(const float* __restrict__ Wout,
                              const float* __restrict__ bout,
                              float* __restrict__ out)
{
    __shared__ float h[2048];
    __shared__ float red[256];
    __shared__ float lg[32];
    int b = blockIdx.x, tid = threadIdx.x;
    for (int i = tid; i < 2048; i += 256) {
        int seg = i >> 9, k = i & 511;           // order: l0f, l0b, l1f, l1b
        h[i] = g_hT[seg][k * Bb + b];
    }
    __syncthreads();
    int e = tid >> 3, part = tid & 7;
    const float4* wrow = (const float4*)(Wout + (size_t)e * 2048 + part * 256);
    const float4* hp   = (const float4*)(h + part * 256);
    float sum = 0.f;
#pragma unroll 8
    for (int i = 0; i < 64; i++) {
        float4 wv = wrow[i], hv = hp[i];
        sum += wv.x*hv.x + wv.y*hv.y + wv.z*hv.z + wv.w*hv.w;
    }
    red[tid] = sum;
    __syncthreads();
    if (part == 0) {
        float sacc = 0.f;
#pragma unroll
        for (int i = 0; i < 8; i++) sacc += red[tid + i];
        lg[e] = sacc + bout[e];
    }
    __syncthreads();
    if (tid < 32) {
        float v = lg[tid];
        float mx = v;
#pragma unroll
        for (int off = 16; off > 0; off >>= 1)
            mx = fmaxf(mx, __shfl_xor_sync(0xffffffffu, mx, off));
        float ex = __expf(v - mx);
        float se = ex;
#pragma unroll
        for (int off = 16; off > 0; off >>= 1)
            se += __shfl_xor_sync(0xffffffffu, se, off);
        out[b * 32 + tid] = v - mx - logf(se);
    }
}

// ---------------- launch ----------------
extern "C" void kernel_launch(void* const* d_in, const int* in_sizes, int n_in,
                              void* d_out, int out_size)
{
    const int*   queries = (const int*)  d_in[0];
    const float* emb     = (const float*)d_in[1];
    const float* Wih0f = (const float*)d_in[2],  *Whh0f = (const float*)d_in[3];
    const float* bih0f = (const float*)d_in[4],  *bhh0f = (const float*)d_in[5];
    const float* Wih0b = (const float*)d_in[6],  *Whh0b = (const float*)d_in[7];
    const float* bih0b = (const float*)d_in[8],  *bhh0b = (const float*)d_in[9];
    const float* Wih1f = (const float*)d_in[10], *Whh1f = (const float*)d_in[11];
    const float* bih1f = (const float*)d_in[12], *bhh1f = (const float*)d_in[13];
    const float* Wih1b = (const float*)d_in[14], *Whh1b = (const float*)d_in[15];
    const float* bih1b = (const float*)d_in[16], *bhh1b = (const float*)d_in[17];
    const float* W_out = (const float*)d_in[18], *b_out = (const float*)d_in[19];

    init_states<<<1024, 256>>>();
    gather_embed<<<Tt*Bb, 64>>>(queries, emb);
    pack_WB<<<8192, 256>>>(Whh0f, Whh0b, Whh1f, Whh1b);

    dim3 gg(G4H/256, (Tt*Bb)/128);   // (8, 64)
    sgemm_tf32w<<<gg, 256>>>(0, 0, Ee,   Wih0f, bih0f, bhh0f);
    sgemm_tf32w<<<gg, 256>>>(0, 1, Ee,   Wih0b, bih0b, bhh0b);

    lstm_persist<<<128, 256>>>(0);

    sgemm_tf32w<<<gg, 256>>>(1, 2, 2*Hh, Wih1f, bih1f, bhh1f);
    sgemm_tf32w<<<gg, 256>>>(1, 3, 2*Hh, Wih1b, bih1b, bhh1b);

    lstm_persist<<<128, 256>>>(1);

    logits_kernel<<<Bb, 256>>>(W_out, b_out, (float*)d_out);
}

// round 16
// speedup vs baseline: 1.1524x; 1.1524x over previous
#include <cuda_runtime.h>
#include <stdint.h>

#define Bb   64
#define Tt   128
#define Ee   256
#define Hh   512
#define G4H  2048
#define GSZ  (Tt*Bb*G4H)   /* 16,777,216 floats per gate buffer */

typedef unsigned long long u64;

// ---------------- scratch (__device__ globals: allocation-free) ----------------
__device__ float  g_x0[Tt*Bb*Ee];                // embedded inputs  [T*B, E]
__device__ float  g_x1[Tt*Bb*2*Hh];              // layer-0 outputs  [T*B, 2H]
__device__ float  g_G[(size_t)4*GSZ];            // gate pre-acts: G0f,G0b,G1f,G1b
__device__ float2 g_WB[4][64*4*64*32];           // Whh tf32 frag pack [sub][g][kb][lane]
__device__ float4 g_hQh[4][2][8192];             // h hi (tf32) frag quads, ping-pong
__device__ uint2  g_hQl2[4][2][8192];            // h lo residual, bf16x2-packed quads
__device__ float  g_hT[4][Hh*Bb];                // final h [k][b] (logits only)
__device__ float  g_c[4][Bb*Hh];                 // c state per sequence
__device__ unsigned g_bar[2][2];                 // [layer][dir] barrier counters

// ---------------- helpers ----------------
__device__ __forceinline__ float sigm(float x) { return 1.f / (1.f + __expf(-x)); }
__device__ __forceinline__ float tanh_fast(float x) {
    float xc = fminf(fmaxf(x, -15.f), 15.f);
    float e = __expf(-2.f * xc);
    return __fdividef(1.f - e, 1.f + e);
}
__device__ __forceinline__ uint32_t f2tf32(float x) {
    uint32_t r; asm("cvt.rna.tf32.f32 %0, %1;" : "=r"(r) : "f"(x)); return r;
}
__device__ __forceinline__ float f2tf32f(float x) { return __uint_as_float(f2tf32(x)); }
__device__ __forceinline__ uint32_t fu(float x) { return __float_as_uint(x); }
__device__ __forceinline__ uint32_t pack_bf2(float c0, float c1) {
    uint32_t w;  // high half = c1, low half = c0
    asm("cvt.rn.bf16x2.f32 %0, %1, %2;" : "=r"(w) : "f"(c1), "f"(c0));
    return w;
}
__device__ __forceinline__ float bf_lo(uint32_t w) { return __uint_as_float(w << 16); }
__device__ __forceinline__ float bf_hi(uint32_t w) { return __uint_as_float(w & 0xffff0000u); }
__device__ __forceinline__ void mma_tf32(float* c,
        uint32_t a0, uint32_t a1, uint32_t a2, uint32_t a3,
        uint32_t b0, uint32_t b1) {
    asm volatile("mma.sync.aligned.m16n8k8.row.col.f32.tf32.tf32.f32 "
        "{%0,%1,%2,%3}, {%4,%5,%6,%7}, {%8,%9}, {%0,%1,%2,%3};"
        : "+f"(c[0]), "+f"(c[1]), "+f"(c[2]), "+f"(c[3])
        : "r"(a0), "r"(a1), "r"(a2), "r"(a3), "r"(b0), "r"(b1));
}

// ---------------- init: zero hQ (both parities, hi+lo), c, barriers ----------------
__global__ void init_states() {
    int i = blockIdx.x * blockDim.x + threadIdx.x;
    if (i < 4*2*8192*4) ((float*)g_hQh)[i] = 0.f;
    if (i < 4*2*8192)   ((uint2*)g_hQl2)[i] = make_uint2(0u, 0u);
    if (i < 4*Bb*Hh)    ((float*)g_c)[i] = 0.f;
    if (i < 4)          ((unsigned*)g_bar)[i] = 0u;
}

// ---------------- Whh -> per-(block,gate,k8) tf32 fragment pack ----------------
__global__ void pack_WB(const float* __restrict__ W0, const float* __restrict__ W1,
                        const float* __restrict__ W2, const float* __restrict__ W3) {
    int idx = blockIdx.x * blockDim.x + threadIdx.x;   // 2,097,152
    int lane = idx & 31;
    int kb   = (idx >> 5) & 63;
    int g    = (idx >> 11) & 3;
    int sub  = (idx >> 13) & 63;
    int seq  = idx >> 19;
    const float* W = (seq == 0) ? W0 : (seq == 1) ? W1 : (seq == 2) ? W2 : W3;
    int gid = lane >> 2, tig = lane & 3;
    int j = g * Hh + sub * 8 + gid;
    int k = kb * 8 + tig;
    float v0 = W[(size_t)j * Hh + k];
    float v1 = W[(size_t)j * Hh + k + 4];
    g_WB[seq][(((sub * 4 + g) * 64 + kb) * 32) + lane] =
        make_float2(f2tf32f(v0), f2tf32f(v1));
}

// ---------------- embedding gather ----------------
__global__ void gather_embed(const int* __restrict__ q, const float* __restrict__ emb) {
    int r = blockIdx.x;              // r = t*B + b
    int b = r & (Bb - 1);
    int t = r >> 6;
    int qi = q[b * Tt + t];
    const float4* src = (const float4*)(emb + (size_t)qi * Ee);
    float4* dst = (float4*)(g_x0 + (size_t)r * Ee);
    dst[threadIdx.x] = src[threadIdx.x];
}

// ---------------- feedforward GEMM: R12 tile shape, PAIRED smem (LDS.64 ops) ----------
// 128x128 tile, BK=16, 8 warps (2m x 4n), warp 64x32, 128 regs -> 2 blocks/SM.
// smem stores (k,k+4) tf32 pairs: A-frag = 2 LDS.64, B-frag = 1 LDS.64.
// Per warp-k8: 12 LDS.64 for 16 mma (was 24 LDS.32).
__global__ __launch_bounds__(256) void sgemm_tf32(int asel, int gsel, int K,
        const float* __restrict__ W,
        const float* __restrict__ b1, const float* __restrict__ b2)
{
    const float* __restrict__ A = asel ? g_x1 : g_x0;
    float* __restrict__ C = g_G + (size_t)gsel * GSZ;

    __shared__ float2 ApS[2][8*132];     // [buf][(kk8*4+tig)*132 + m]
    __shared__ float2 BpS[2][8*132];     // [buf][(kk8*4+tig)*132 + n]

    const int tid = threadIdx.x;
    const int m0 = blockIdx.y * 128, n0 = blockIdx.x * 128;
    const int w = tid >> 5, lane = tid & 31;
    const int gid = lane >> 2, tig = lane & 3;
    const int wm = (w & 1) * 64;
    const int wn = (w >> 1) * 32;

    float acc[4][4][4];
#pragma unroll
    for (int mt = 0; mt < 4; mt++)
#pragma unroll
        for (int nt = 0; nt < 4; nt++)
#pragma unroll
            for (int i = 0; i < 4; i++) acc[mt][nt][i] = 0.f;

    const int sr = tid >> 2;             // 0..63
    const int sc = (tid & 3) * 4;        // 0,4,8,12
    const int kk8s = sc >> 3;            // 0 or 1
    const int cidx = (sc >> 2) & 1;      // pair component (.x or .y)
    const float* Ar0 = A + (size_t)(m0 + sr) * K + sc;
    const float* Ar1 = A + (size_t)(m0 + sr + 64) * K + sc;
    const float* Wr0 = W + (size_t)(n0 + sr) * K + sc;
    const float* Wr1 = W + (size_t)(n0 + sr + 64) * K + sc;

#define STP(bsel, va0, va1, vb0, vb1) { \
    float* AF = (float*)ApS[bsel]; \
    float* BF = (float*)BpS[bsel]; \
    AF[((kk8s*4+0)*132 + sr)*2 + cidx]      = f2tf32f(va0.x); \
    AF[((kk8s*4+1)*132 + sr)*2 + cidx]      = f2tf32f(va0.y); \
    AF[((kk8s*4+2)*132 + sr)*2 + cidx]      = f2tf32f(va0.z); \
    AF[((kk8s*4+3)*132 + sr)*2 + cidx]      = f2tf32f(va0.w); \
    AF[((kk8s*4+0)*132 + sr + 64)*2 + cidx] = f2tf32f(va1.x); \
    AF[((kk8s*4+1)*132 + sr + 64)*2 + cidx] = f2tf32f(va1.y); \
    AF[((kk8s*4+2)*132 + sr + 64)*2 + cidx] = f2tf32f(va1.z); \
    AF[((kk8s*4+3)*132 + sr + 64)*2 + cidx] = f2tf32f(va1.w); \
    BF[((kk8s*4+0)*132 + sr)*2 + cidx]      = f2tf32f(vb0.x); \
    BF[((kk8s*4+1)*132 + sr)*2 + cidx]      = f2tf32f(vb0.y); \
    BF[((kk8s*4+2)*132 + sr)*2 + cidx]      = f2tf32f(vb0.z); \
    BF[((kk8s*4+3)*132 + sr)*2 + cidx]      = f2tf32f(vb0.w); \
    BF[((kk8s*4+0)*132 + sr + 64)*2 + cidx] = f2tf32f(vb1.x); \
    BF[((kk8s*4+1)*132 + sr + 64)*2 + cidx] = f2tf32f(vb1.y); \
    BF[((kk8s*4+2)*132 + sr + 64)*2 + cidx] = f2tf32f(vb1.z); \
    BF[((kk8s*4+3)*132 + sr + 64)*2 + cidx] = f2tf32f(vb1.w); }

    {
        float4 va0 = *(const float4*)Ar0;
        float4 va1 = *(const float4*)Ar1;
        float4 vb0 = *(const float4*)Wr0;
        float4 vb1 = *(const float4*)Wr1;
        STP(0, va0, va1, vb0, vb1);
    }
    __syncthreads();

    int buf = 0;
    for (int kt = 0; kt < K; kt += 16) {
        float4 va0, va1, vb0, vb1;
        bool more = (kt + 16 < K);
        if (more) {
            va0 = *(const float4*)(Ar0 + kt + 16);
            va1 = *(const float4*)(Ar1 + kt + 16);
            vb0 = *(const float4*)(Wr0 + kt + 16);
            vb1 = *(const float4*)(Wr1 + kt + 16);
        }
#pragma unroll
        for (int kk8 = 0; kk8 < 2; kk8++) {
            const float2* pa = &ApS[buf][(kk8*4 + tig)*132 + wm + gid];
            const float2* pb = &BpS[buf][(kk8*4 + tig)*132 + wn + gid];
            float2 pa0[4], pa1[4], pbv[4];
#pragma unroll
            for (int mt = 0; mt < 4; mt++) {
                pa0[mt] = pa[mt*16];
                pa1[mt] = pa[mt*16 + 8];
            }
#pragma unroll
            for (int nt = 0; nt < 4; nt++) pbv[nt] = pb[nt*8];
#pragma unroll
            for (int mt = 0; mt < 4; mt++)
#pragma unroll
                for (int nt = 0; nt < 4; nt++)
                    mma_tf32(acc[mt][nt],
                             fu(pa0[mt].x), fu(pa1[mt].x), fu(pa0[mt].y), fu(pa1[mt].y),
                             fu(pbv[nt].x), fu(pbv[nt].y));
        }
        if (more) {
            STP(buf ^ 1, va0, va1, vb0, vb1);
            __syncthreads();
            buf ^= 1;
        }
    }
#undef STP

#pragma unroll
    for (int nt = 0; nt < 4; nt++) {
        int gn = n0 + wn + nt * 8 + 2 * tig;
        float bs0 = b1[gn]   + b2[gn];
        float bs1 = b1[gn+1] + b2[gn+1];
#pragma unroll
        for (int mt = 0; mt < 4; mt++) {
            int gm = m0 + wm + mt * 16 + gid;
            float* c0 = C + (size_t)gm * G4H + gn;
            float* c1 = C + (size_t)(gm + 8) * G4H + gn;
            c0[0] = acc[mt][nt][0] + bs0;
            c0[1] = acc[mt][nt][1] + bs1;
            c1[0] = acc[mt][nt][2] + bs0;
            c1[1] = acc[mt][nt][3] + bs1;
        }
    }
}

// ---------------- per-direction software barrier (release/acquire) ----------------
__device__ __forceinline__ void dirbar(unsigned* ctr, unsigned target) {
    __syncthreads();
    if (threadIdx.x == 0) {
        asm volatile("red.release.gpu.global.add.u32 [%0], %1;"
                     :: "l"(ctr), "r"(1u) : "memory");
        unsigned v;
        do {
            asm volatile("ld.acquire.gpu.global.u32 %0, [%1];"
                         : "=r"(v) : "l"(ctr) : "memory");
            if (v >= target) break;
            __nanosleep(32);
        } while (true);
    }
    __syncthreads();
}

// ---------------- persistent recurrence (R14: split-h tf32, bf16 lo, staged WB) -------
__global__ __launch_bounds__(256, 1) void lstm_persist(int layer)
{
    __shared__ float gs[2][64 * 34];             // 17,408 B
    __shared__ float sh_hi[512];                 // h hi staging (frag order)
    __shared__ float sh_lo[512];                 // h lo staging (frag order)

    const int tid = threadIdx.x;
    const int dir = blockIdx.x >> 6;
    const int sub = blockIdx.x & 63;
    const int seq = layer * 2 + dir;
    const int w = tid >> 5, lane = tid & 31;
    const int kh = w & 1, mt = w >> 1;           // k-half, m16 tile
    const int gid = lane >> 2, tig = lane & 3;
    const int n0 = sub * 8;

    const float2* __restrict__ WB = g_WB[seq];
    float* __restrict__ cs = g_c[seq];
    const float* __restrict__ Gseq = g_G + (size_t)seq * GSZ;
    unsigned* bar = &g_bar[layer][dir];

    const int ew_m = tid >> 2;                   // 0..63
    const int u2 = (tid & 3) * 2;                // 0,2,4,6

    const float2* Bp0 = WB + (size_t)(((sub * 4 + 0) * 64) * 32) + lane;
    const float2* Bp1 = WB + (size_t)(((sub * 4 + 1) * 64) * 32) + lane;
    const float2* Bp2 = WB + (size_t)(((sub * 4 + 2) * 64) * 32) + lane;
    const float2* Bp3 = WB + (size_t)(((sub * 4 + 3) * 64) * 32) + lane;

#define IDXA(kb) ((((kb) * 4 + tig) * 4 + mt) * 8 + gid)

    for (int s = 0; s < Tt; s++) {
        const int t = dir ? (Tt - 1 - s) : s;
        const int p = s & 1;
        const float4* __restrict__ Hhi = g_hQh[seq][p];
        const uint2*  __restrict__ Hlo = g_hQl2[seq][p];
        float4* __restrict__ WHq = g_hQh[seq][p ^ 1];
        uint2*  __restrict__ WLq = g_hQl2[seq][p ^ 1];

        // ---------- prefetch gate pre-acts (DRAM) ----------
        const float* Gt = Gseq + (size_t)t * Bb * G4H;
        float2 gpre[4];
#pragma unroll
        for (int g = 0; g < 4; g++)
            gpre[g] = __ldcg((const float2*)&Gt[(size_t)ew_m * G4H + g * Hh + n0 + u2]);

        // ---------- tensor-core GEMM over this k-half ----------
        float acc[4][4];
#pragma unroll
        for (int g = 0; g < 4; g++)
#pragma unroll
            for (int i = 0; i < 4; i++) acc[g][i] = 0.f;

        const int kb0 = kh * 32;
        float4 ah = __ldcg(Hhi + IDXA(kb0));
        uint2  alw = __ldcg(Hlo + IDXA(kb0));
#pragma unroll 4
        for (int i = 0; i < 32; i++) {
            const int kb = kb0 + i;
            float4 ah2; uint2 alw2;
            if (i + 1 < 32) {
                ah2  = __ldcg(Hhi + IDXA(kb + 1));
                alw2 = __ldcg(Hlo + IDXA(kb + 1));
            }
            float2 b0 = Bp0[kb * 32];
            float2 b1 = Bp1[kb * 32];
            float2 b2 = Bp2[kb * 32];
            float2 b3 = Bp3[kb * 32];
            float l0 = bf_lo(alw.x), l1 = bf_hi(alw.x);
            float l2 = bf_lo(alw.y), l3 = bf_hi(alw.y);
            mma_tf32(acc[0], fu(ah.x), fu(ah.y), fu(ah.z), fu(ah.w), fu(b0.x), fu(b0.y));
            mma_tf32(acc[1], fu(ah.x), fu(ah.y), fu(ah.z), fu(ah.w), fu(b1.x), fu(b1.y));
            mma_tf32(acc[2], fu(ah.x), fu(ah.y), fu(ah.z), fu(ah.w), fu(b2.x), fu(b2.y));
            mma_tf32(acc[3], fu(ah.x), fu(ah.y), fu(ah.z), fu(ah.w), fu(b3.x), fu(b3.y));
            mma_tf32(acc[0], fu(l0), fu(l1), fu(l2), fu(l3), fu(b0.x), fu(b0.y));
            mma_tf32(acc[1], fu(l0), fu(l1), fu(l2), fu(l3), fu(b1.x), fu(b1.y));
            mma_tf32(acc[2], fu(l0), fu(l1), fu(l2), fu(l3), fu(b2.x), fu(b2.y));
            mma_tf32(acc[3], fu(l0), fu(l1), fu(l2), fu(l3), fu(b3.x), fu(b3.y));
            ah = ah2; alw = alw2;
        }

        // ---------- epilogue: write k-half slab ----------
        {
            int mrow = mt * 16 + gid;
#pragma unroll
            for (int g = 0; g < 4; g++) {
                *(float2*)&gs[kh][mrow * 34 + g * 8 + 2 * tig] =
                    make_float2(acc[g][0], acc[g][1]);
                *(float2*)&gs[kh][(mrow + 8) * 34 + g * 8 + 2 * tig] =
                    make_float2(acc[g][2], acc[g][3]);
            }
        }
        __syncthreads();

        // ---------- k-reduce (2 slabs) + input proj + fused LSTM elementwise ----------
        {
            float2 pre[4];
#pragma unroll
            for (int g = 0; g < 4; g++) {
                float2 p0 = *(const float2*)&gs[0][ew_m * 34 + g * 8 + u2];
                float2 p1 = *(const float2*)&gs[1][ew_m * 34 + g * 8 + u2];
                pre[g] = make_float2(gpre[g].x + p0.x + p1.x, gpre[g].y + p0.y + p1.y);
            }
            int ci = ew_m * Hh + n0 + u2;
            float2 c2 = *(float2*)&cs[ci];
            float hn[2], cn[2];
#pragma unroll
            for (int e = 0; e < 2; e++) {
                float pi = e ? pre[0].y : pre[0].x;
                float pf = e ? pre[1].y : pre[1].x;
                float pg = e ? pre[2].y : pre[2].x;
                float po = e ? pre[3].y : pre[3].x;
                float cp = e ? c2.y : c2.x;
                float i_s = sigm(pi), f_s = sigm(pf);
                float g_t = tanh_fast(pg), o_s = sigm(po);
                cn[e] = f_s * cp + i_s * g_t;
                hn[e] = o_s * tanh_fast(cn[e]);
            }
            *(float2*)&cs[ci] = make_float2(cn[0], cn[1]);
            if (layer == 0)
                *(float2*)&g_x1[((size_t)t * Bb + ew_m) * (2*Hh) + dir * Hh + n0 + u2] =
                    make_float2(hn[0], hn[1]);
            // stage hi/lo into smem in fragment order
#pragma unroll
            for (int e = 0; e < 2; e++) {
                int u = u2 + e;
                int tg = u & 3, zs = u >> 2;
                int comp = zs * 2 + ((ew_m >> 3) & 1);
                int idx = ((tg * 4 + (ew_m >> 4)) * 8 + (ew_m & 7)) * 4 + comp;
                float hv = f2tf32f(hn[e]);
                sh_hi[idx] = hv;
                sh_lo[idx] = hn[e] - hv;
            }
            if (s == Tt - 1) {
                g_hT[seq][(n0 + u2) * Bb + ew_m]     = hn[0];
                g_hT[seq][(n0 + u2 + 1) * Bb + ew_m] = hn[1];
            }
        }
        __syncthreads();

        // ---------- vectorized fragment writeback (coalesced) ----------
        if (tid < 128) {
            WHq[sub * 128 + tid] = *(const float4*)&sh_hi[tid * 4];
        } else {
            int qi = tid - 128;
            const float* lp = &sh_lo[qi * 4];
            uint2 ov;
            ov.x = pack_bf2(lp[0], lp[1]);
            ov.y = pack_bf2(lp[2], lp[3]);
            WLq[sub * 128 + qi] = ov;
        }

        dirbar(bar, 64u * (s + 1));   // h_{s+1} (opposite parity) complete before s+1
    }
#undef IDXA
}

// ---------------- output head: logits + log_softmax ----------------
__global__ void logits_kernel(const float* __restrict__ Wout,
                              const float* __restrict__ bout,
                              float* __restrict__ out)
{
    __shared__ float h[2048];
    __shared__ float red[256];
    __shared__ float lg[32];
    int b = blockIdx.x, tid = threadIdx.x;
    for (int i = tid; i < 2048; i += 256) {
        int seg = i >> 9, k = i & 511;           // order: l0f, l0b, l1f, l1b
        h[i] = g_hT[seg][k * Bb + b];
    }
    __syncthreads();
    int e = tid >> 3, part = tid & 7;
    const float4* wrow = (const float4*)(Wout + (size_t)e * 2048 + part * 256);
    const float4* hp   = (const float4*)(h + part * 256);
    float sum = 0.f;
#pragma unroll 8
    for (int i = 0; i < 64; i++) {
        float4 wv = wrow[i], hv = hp[i];
        sum += wv.x*hv.x + wv.y*hv.y + wv.z*hv.z + wv.w*hv.w;
    }
    red[tid] = sum;
    __syncthreads();
    if (part == 0) {
        float sacc = 0.f;
#pragma unroll
        for (int i = 0; i < 8; i++) sacc += red[tid + i];
        lg[e] = sacc + bout[e];
    }
    __syncthreads();
    if (tid < 32) {
        float v = lg[tid];
        float mx = v;
#pragma unroll
        for (int off = 16; off > 0; off >>= 1)
            mx = fmaxf(mx, __shfl_xor_sync(0xffffffffu, mx, off));
        float ex = __expf(v - mx);
        float se = ex;
#pragma unroll
        for (int off = 16; off > 0; off >>= 1)
            se += __shfl_xor_sync(0xffffffffu, se, off);
        out[b * 32 + tid] = v - mx - logf(se);
    }
}

// ---------------- launch ----------------
extern "C" void kernel_launch(void* const* d_in, const int* in_sizes, int n_in,
                              void* d_out, int out_size)
{
    const int*   queries = (const int*)  d_in[0];
    const float* emb     = (const float*)d_in[1];
    const float* Wih0f = (const float*)d_in[2],  *Whh0f = (const float*)d_in[3];
    const float* bih0f = (const float*)d_in[4],  *bhh0f = (const float*)d_in[5];
    const float* Wih0b = (const float*)d_in[6],  *Whh0b = (const float*)d_in[7];
    const float* bih0b = (const float*)d_in[8],  *bhh0b = (const float*)d_in[9];
    const float* Wih1f = (const float*)d_in[10], *Whh1f = (const float*)d_in[11];
    const float* bih1f = (const float*)d_in[12], *bhh1f = (const float*)d_in[13];
    const float* Wih1b = (const float*)d_in[14], *Whh1b = (const float*)d_in[15];
    const float* bih1b = (const float*)d_in[16], *bhh1b = (const float*)d_in[17];
    const float* W_out = (const float*)d_in[18], *b_out = (const float*)d_in[19];

    init_states<<<1024, 256>>>();
    gather_embed<<<Tt*Bb, 64>>>(queries, emb);
    pack_WB<<<8192, 256>>>(Whh0f, Whh0b, Whh1f, Whh1b);

    dim3 gg(G4H/128, (Tt*Bb)/128);   // (16, 64)
    sgemm_tf32<<<gg, 256>>>(0, 0, Ee,   Wih0f, bih0f, bhh0f);
    sgemm_tf32<<<gg, 256>>>(0, 1, Ee,   Wih0b, bih0b, bhh0b);

    lstm_persist<<<128, 256>>>(0);

    sgemm_tf32<<<gg, 256>>>(1, 2, 2*Hh, Wih1f, bih1f, bhh1f);
    sgemm_tf32<<<gg, 256>>>(1, 3, 2*Hh, Wih1b, bih1b, bhh1b);

    lstm_persist<<<128, 256>>>(1);

    logits_kernel<<<Bb, 256>>>(W_out, b_out, (float*)d_out);
}